// round 2
// baseline (speedup 1.0000x reference)
#include <cuda_runtime.h>
#include <cstdint>

// Problem constants (fixed by reference)
#define B_  32
#define T_  1024
#define D_  256
#define NM  80
#define MM  8192    // MAX_MEL = T_TEXT * MAX_DUR

// Device scratch (no allocations allowed)
__device__ int   g_idx[B_ * MM];      // frame -> token index (only valid frames written)
__device__ int   g_len[B_];           // valid mel length per batch
__device__ float g_mu [B_ * NM * T_]; // per-token mel projection, layout [b][n][t]

// ---------------------------------------------------------------------------
// Packed fp32x2 helpers (Blackwell sm_100+)
// ---------------------------------------------------------------------------
__device__ __forceinline__ unsigned long long fma2(unsigned long long a,
                                                   unsigned long long b,
                                                   unsigned long long c) {
    unsigned long long d;
    asm("fma.rn.f32x2 %0, %1, %2, %3;" : "=l"(d) : "l"(a), "l"(b), "l"(c));
    return d;
}
__device__ __forceinline__ unsigned long long pack2(float lo, float hi) {
    unsigned long long r;
    asm("mov.b64 %0, {%1, %2};" : "=l"(r) : "f"(lo), "f"(hi));
    return r;
}
__device__ __forceinline__ void unpack2(unsigned long long v, float& lo, float& hi) {
    asm("mov.b64 {%0, %1}, %2;" : "=f"(lo), "=f"(hi) : "l"(v));
}

// ---------------------------------------------------------------------------
// K2 (fused): token GEMM + duration scan.
//   blockIdx.x < 16 : GEMM tile  g_mu[b][n][t] = sum_d W[n][d]*E[b][t][d] + b_mu[n]
//   blockIdx.x ==16 : per-batch warp-shuffle scan of durations -> g_idx/g_len
// GEMM: 64-token tile, 80 mel rows, 256 thr as 16(t)x16(n), thread tile 5n x 4t,
// inner product via fma.rn.f32x2 (pairs over tokens).
// ---------------------------------------------------------------------------
#define TT 64   // token tile
#define KC 64   // k chunk
#define EPAD 68 // sE row stride in floats (16B aligned, low-conflict)

__global__ __launch_bounds__(256) void gemm_scan_kernel(
    const float* __restrict__ E, const float* __restrict__ W,
    const float* __restrict__ bmu, const int* __restrict__ dur) {
    const int b   = blockIdx.y;
    const int tid = threadIdx.x;

    if (blockIdx.x == T_ / TT) {
        // ---- scan branch: 256 threads, 4 durations each ----
        __shared__ int wsum[8];
        const int lane = tid & 31;
        const int wid  = tid >> 5;
        int4 d4 = *reinterpret_cast<const int4*>(dur + b * T_ + tid * 4);
        int s = d4.x + d4.y + d4.z + d4.w;
#pragma unroll
        for (int off = 1; off < 32; off <<= 1) {
            int v = __shfl_up_sync(0xffffffffu, s, off);
            if (lane >= off) s += v;
        }
        if (lane == 31) wsum[wid] = s;
        __syncthreads();
        int base = 0;
#pragma unroll
        for (int w = 0; w < 8; ++w) base += (w < wid) ? wsum[w] : 0;
        const int end3  = base + s;         // inclusive cum through elem 4*tid+3
        const int start = end3 - (d4.x + d4.y + d4.z + d4.w);
        const int c0 = start + d4.x;
        const int c1 = c0 + d4.y;
        const int c2 = c1 + d4.z;
        int* ib = g_idx + b * MM;
        const int t0 = tid * 4;
        for (int p = start; p < c0; ++p) ib[p] = t0 + 0;
        for (int p = c0;    p < c1; ++p) ib[p] = t0 + 1;
        for (int p = c1;    p < c2; ++p) ib[p] = t0 + 2;
        for (int p = c2;    p < end3; ++p) ib[p] = t0 + 3;
        if (tid == 255) g_len[b] = end3;
        return;
    }

    // ---- GEMM branch ----
    const int t0 = blockIdx.x * TT;
    const int tx = tid & 15;   // token dir (4 tokens each)
    const int ty = tid >> 4;   // mel dir   (5 mels each)

    __shared__ float sW[NM * KC];      // [n][k], row stride KC
    __shared__ float sE[KC * EPAD];    // [k][t], row stride EPAD

    unsigned long long acc01[5], acc23[5];
    const unsigned long long z = pack2(0.0f, 0.0f);
#pragma unroll
    for (int i = 0; i < 5; ++i) { acc01[i] = z; acc23[i] = z; }

    for (int kc = 0; kc < D_; kc += KC) {
        // Load W chunk: 80x64 floats, float4-vectorized, coalesced.
        for (int q = tid; q < NM * (KC / 4); q += 256) {
            const int n  = q >> 4;          // KC/4 = 16 float4 per row
            const int kf = q & 15;
            float4 v = *reinterpret_cast<const float4*>(W + n * D_ + kc + kf * 4);
            *reinterpret_cast<float4*>(sW + n * KC + kf * 4) = v;
        }
        // Load E chunk transposed: read coalesced float4 over d, scatter to [k][t].
        for (int q = tid; q < TT * (KC / 4); q += 256) {
            const int t  = q >> 4;
            const int kf = q & 15;
            float4 v = *reinterpret_cast<const float4*>(
                E + ((size_t)b * T_ + t0 + t) * D_ + kc + kf * 4);
            const int k = kf * 4;
            sE[(k + 0) * EPAD + t] = v.x;
            sE[(k + 1) * EPAD + t] = v.y;
            sE[(k + 2) * EPAD + t] = v.z;
            sE[(k + 3) * EPAD + t] = v.w;
        }
        __syncthreads();

#pragma unroll 8
        for (int k = 0; k < KC; ++k) {
            ulonglong2 e = *reinterpret_cast<const ulonglong2*>(&sE[k * EPAD + tx * 4]);
#pragma unroll
            for (int i = 0; i < 5; ++i) {
                const float w = sW[(ty * 5 + i) * KC + k];
                const unsigned long long wp = pack2(w, w);
                acc01[i] = fma2(wp, e.x, acc01[i]);
                acc23[i] = fma2(wp, e.y, acc23[i]);
            }
        }
        __syncthreads();
    }

    // Epilogue: add bias, store float4 to g_mu[b][n][t]
#pragma unroll
    for (int i = 0; i < 5; ++i) {
        const int n = ty * 5 + i;
        const float bv = bmu[n];
        float4 r;
        unpack2(acc01[i], r.x, r.y);
        unpack2(acc23[i], r.z, r.w);
        r.x += bv; r.y += bv; r.z += bv; r.w += bv;
        *reinterpret_cast<float4*>(g_mu + ((size_t)b * NM + n) * T_ + t0 + tx * 4) = r;
    }
}

// ---------------------------------------------------------------------------
// K3: scatter per-token mu columns into out[b][n][p], 4 frames per thread via
// float4 stores; zero padding frames; append mel_mask floats if present.
// ---------------------------------------------------------------------------
__global__ __launch_bounds__(128) void upsample_store(float* __restrict__ out,
                                                      int write_mask) {
    const int b  = blockIdx.y;
    const int p0 = (blockIdx.x * 128 + threadIdx.x) * 4;
    const int L  = g_len[b];

    int4 t4 = *reinterpret_cast<const int4*>(g_idx + b * MM + p0);
    const bool v0 = (p0 + 0) < L;
    const bool v1 = (p0 + 1) < L;
    const bool v2 = (p0 + 2) < L;
    const bool v3 = (p0 + 3) < L;
    // guard against stale/garbage indices in the padding region
    if (!v0) t4.x = 0;
    if (!v1) t4.y = 0;
    if (!v2) t4.z = 0;
    if (!v3) t4.w = 0;

    const float* mb = g_mu + (size_t)b * NM * T_;
    float* obase = out + (size_t)b * NM * MM + p0;

#pragma unroll 8
    for (int n = 0; n < NM; ++n) {
        const float* r = mb + (size_t)n * T_;
        float4 o;
        o.x = v0 ? r[t4.x] : 0.0f;
        o.y = v1 ? r[t4.y] : 0.0f;
        o.z = v2 ? r[t4.z] : 0.0f;
        o.w = v3 ? r[t4.w] : 0.0f;
        *reinterpret_cast<float4*>(obase + (size_t)n * MM) = o;
    }
    if (write_mask) {
        float4 m;
        m.x = v0 ? 1.0f : 0.0f;
        m.y = v1 ? 1.0f : 0.0f;
        m.z = v2 ? 1.0f : 0.0f;
        m.w = v3 ? 1.0f : 0.0f;
        *reinterpret_cast<float4*>(out + (size_t)B_ * NM * MM + (size_t)b * MM + p0) = m;
    }
}

// ---------------------------------------------------------------------------
extern "C" void kernel_launch(void* const* d_in, const int* in_sizes, int n_in,
                              void* d_out, int out_size) {
    const float* E   = nullptr;
    const int*   dur = nullptr;
    const float* W   = nullptr;
    const float* bmu = nullptr;
    for (int i = 0; i < n_in; ++i) {
        switch (in_sizes[i]) {
            case B_ * T_ * D_: E   = (const float*)d_in[i]; break;
            case B_ * T_:      dur = (const int*)  d_in[i]; break;
            case NM * D_:      W   = (const float*)d_in[i]; break;
            case NM:           bmu = (const float*)d_in[i]; break;
            default: break;
        }
    }
    float* out = (float*)d_out;
    const int mu_elems = B_ * NM * MM;          // 20,971,520
    const int write_mask = (out_size >= mu_elems + B_ * MM) ? 1 : 0;

    gemm_scan_kernel<<<dim3(T_ / TT + 1, B_), 256>>>(E, W, bmu, dur);
    upsample_store<<<dim3(MM / (128 * 4), B_), 128>>>(out, write_mask);
}

// round 4
// speedup vs baseline: 1.0443x; 1.0443x over previous
#include <cuda_runtime.h>
#include <cstdint>

// Problem constants (fixed by reference)
#define B_  32
#define T_  1024
#define D_  256
#define NM  80
#define MM  8192    // MAX_MEL = T_TEXT * MAX_DUR

// Device scratch (no allocations allowed)
__device__ int   g_idx[B_ * MM];      // frame -> token index (only valid frames written)
__device__ int   g_len[B_];           // valid mel length per batch
__device__ float g_mu [B_ * NM * T_]; // per-token mel projection, layout [b][n][t]

// ---------------------------------------------------------------------------
// Packed fp32x2 helpers (Blackwell sm_100+)
// ---------------------------------------------------------------------------
__device__ __forceinline__ unsigned long long fma2(unsigned long long a,
                                                   unsigned long long b,
                                                   unsigned long long c) {
    unsigned long long d;
    asm("fma.rn.f32x2 %0, %1, %2, %3;" : "=l"(d) : "l"(a), "l"(b), "l"(c));
    return d;
}
__device__ __forceinline__ unsigned long long pack2(float lo, float hi) {
    unsigned long long r;
    asm("mov.b64 %0, {%1, %2};" : "=l"(r) : "f"(lo), "f"(hi));
    return r;
}
__device__ __forceinline__ void unpack2(unsigned long long v, float& lo, float& hi) {
    asm("mov.b64 {%0, %1}, %2;" : "=f"(lo), "=f"(hi) : "l"(v));
}

// ---------------------------------------------------------------------------
// K2 (fused): token GEMM + duration scan.
//   blockIdx.x < 16 : GEMM tile  g_mu[b][n][t] = sum_d W[n][d]*E[b][t][d] + b_mu[n]
//   blockIdx.x ==16 : per-batch warp-shuffle scan of durations -> g_idx/g_len
// GEMM: 64-token tile, 80 mel rows, 256 thr as 16(t)x16(n), thread tile 5n x 4t.
// W staged in smem PRE-DUPLICATED as (w,w) 64-bit pairs so the inner loop is
// pure LDS + fma.rn.f32x2 with no packing overhead. KC=32 to fit 48KB smem.
// ---------------------------------------------------------------------------
#define TT 64   // token tile
#define KC 32   // k chunk  (smem: 80*32*8 + 32*68*4 = 29184 B)
#define EPAD 68 // sE row stride in floats (16B aligned, low-conflict)

__global__ __launch_bounds__(256) void gemm_scan_kernel(
    const float* __restrict__ E, const float* __restrict__ W,
    const float* __restrict__ bmu, const int* __restrict__ dur) {
    const int b   = blockIdx.y;
    const int tid = threadIdx.x;

    if (blockIdx.x == T_ / TT) {
        // ---- scan branch: 256 threads, 4 durations each ----
        __shared__ int wsum[8];
        const int lane = tid & 31;
        const int wid  = tid >> 5;
        int4 d4 = *reinterpret_cast<const int4*>(dur + b * T_ + tid * 4);
        int s = d4.x + d4.y + d4.z + d4.w;
#pragma unroll
        for (int off = 1; off < 32; off <<= 1) {
            int v = __shfl_up_sync(0xffffffffu, s, off);
            if (lane >= off) s += v;
        }
        if (lane == 31) wsum[wid] = s;
        __syncthreads();
        int base = 0;
#pragma unroll
        for (int w = 0; w < 8; ++w) base += (w < wid) ? wsum[w] : 0;
        const int end3  = base + s;         // inclusive cum through elem 4*tid+3
        const int start = end3 - (d4.x + d4.y + d4.z + d4.w);
        const int c0 = start + d4.x;
        const int c1 = c0 + d4.y;
        const int c2 = c1 + d4.z;
        int* ib = g_idx + b * MM;
        const int t0 = tid * 4;
        for (int p = start; p < c0; ++p) ib[p] = t0 + 0;
        for (int p = c0;    p < c1; ++p) ib[p] = t0 + 1;
        for (int p = c1;    p < c2; ++p) ib[p] = t0 + 2;
        for (int p = c2;    p < end3; ++p) ib[p] = t0 + 3;
        if (tid == 255) g_len[b] = end3;
        return;
    }

    // ---- GEMM branch ----
    const int t0 = blockIdx.x * TT;
    const int tx = tid & 15;   // token dir (4 tokens each)
    const int ty = tid >> 4;   // mel dir   (5 mels each)

    __shared__ unsigned long long sW2[NM * KC]; // [n][k] duplicated pairs (w,w)
    __shared__ float sE[KC * EPAD];             // [k][t], row stride EPAD

    unsigned long long acc01[5], acc23[5];
    const unsigned long long z = pack2(0.0f, 0.0f);
#pragma unroll
    for (int i = 0; i < 5; ++i) { acc01[i] = z; acc23[i] = z; }

    for (int kc = 0; kc < D_; kc += KC) {
        // Load W chunk: 80x32 floats, duplicate each into (w,w) ulonglong.
        // KC/4 = 8 float4 per row.
        for (int q = tid; q < NM * (KC / 4); q += 256) {
            const int n  = q >> 3;
            const int kf = q & 7;
            float4 v = *reinterpret_cast<const float4*>(W + n * D_ + kc + kf * 4);
            ulonglong2 p0, p1;
            p0.x = pack2(v.x, v.x); p0.y = pack2(v.y, v.y);
            p1.x = pack2(v.z, v.z); p1.y = pack2(v.w, v.w);
            *reinterpret_cast<ulonglong2*>(sW2 + n * KC + kf * 4)     = p0;
            *reinterpret_cast<ulonglong2*>(sW2 + n * KC + kf * 4 + 2) = p1;
        }
        // Load E chunk transposed: read coalesced float4 over d, scatter to [k][t].
        for (int q = tid; q < TT * (KC / 4); q += 256) {
            const int t  = q >> 3;
            const int kf = q & 7;
            float4 v = *reinterpret_cast<const float4*>(
                E + ((size_t)b * T_ + t0 + t) * D_ + kc + kf * 4);
            const int k = kf * 4;
            sE[(k + 0) * EPAD + t] = v.x;
            sE[(k + 1) * EPAD + t] = v.y;
            sE[(k + 2) * EPAD + t] = v.z;
            sE[(k + 3) * EPAD + t] = v.w;
        }
        __syncthreads();

#pragma unroll 8
        for (int k = 0; k < KC; ++k) {
            ulonglong2 e = *reinterpret_cast<const ulonglong2*>(&sE[k * EPAD + tx * 4]);
#pragma unroll
            for (int i = 0; i < 5; ++i) {
                const unsigned long long wp = sW2[(ty * 5 + i) * KC + k];
                acc01[i] = fma2(wp, e.x, acc01[i]);
                acc23[i] = fma2(wp, e.y, acc23[i]);
            }
        }
        __syncthreads();
    }

    // Epilogue: add bias, store float4 to g_mu[b][n][t]
#pragma unroll
    for (int i = 0; i < 5; ++i) {
        const int n = ty * 5 + i;
        const float bv = bmu[n];
        float4 r;
        unpack2(acc01[i], r.x, r.y);
        unpack2(acc23[i], r.z, r.w);
        r.x += bv; r.y += bv; r.z += bv; r.w += bv;
        *reinterpret_cast<float4*>(g_mu + ((size_t)b * NM + n) * T_ + t0 + tx * 4) = r;
    }
}

// ---------------------------------------------------------------------------
// K3: scatter per-token mu columns into out[b][n][p].
// Block = (128-frame tile, batch); 256 threads cover 81 rows (80 mu + mask)
// x 32 float4 groups. Frame->token indices staged in smem once per block.
// ---------------------------------------------------------------------------
__global__ __launch_bounds__(256) void upsample_store(float* __restrict__ out,
                                                      int write_mask) {
    const int b  = blockIdx.y;
    const int f0 = blockIdx.x * 128;
    __shared__ int sidx[128];
    const int L = g_len[b];

    if (threadIdx.x < 128) {
        const int p = f0 + threadIdx.x;
        const int t = g_idx[b * MM + p];
        sidx[threadIdx.x] = (p < L) ? t : -1;   // -1 marks padding frame
    }
    __syncthreads();

    const float* mb = g_mu + (size_t)b * NM * T_;
    float* ob = out + (size_t)b * NM * MM + f0;
    float* maskb = out + (size_t)B_ * NM * MM + (size_t)b * MM + f0;

    for (int q = threadIdx.x; q < 81 * 32; q += 256) {
        const int n = q >> 5;
        const int g = (q & 31) * 4;
        const int t0 = sidx[g + 0];
        const int t1 = sidx[g + 1];
        const int t2 = sidx[g + 2];
        const int t3 = sidx[g + 3];
        if (n < NM) {
            const float* r = mb + (size_t)n * T_;
            float4 o;
            o.x = (t0 >= 0) ? r[t0] : 0.0f;
            o.y = (t1 >= 0) ? r[t1] : 0.0f;
            o.z = (t2 >= 0) ? r[t2] : 0.0f;
            o.w = (t3 >= 0) ? r[t3] : 0.0f;
            *reinterpret_cast<float4*>(ob + (size_t)n * MM + g) = o;
        } else if (write_mask) {
            float4 m;
            m.x = (t0 >= 0) ? 1.0f : 0.0f;
            m.y = (t1 >= 0) ? 1.0f : 0.0f;
            m.z = (t2 >= 0) ? 1.0f : 0.0f;
            m.w = (t3 >= 0) ? 1.0f : 0.0f;
            *reinterpret_cast<float4*>(maskb + g) = m;
        }
    }
}

// ---------------------------------------------------------------------------
extern "C" void kernel_launch(void* const* d_in, const int* in_sizes, int n_in,
                              void* d_out, int out_size) {
    const float* E   = nullptr;
    const int*   dur = nullptr;
    const float* W   = nullptr;
    const float* bmu = nullptr;
    for (int i = 0; i < n_in; ++i) {
        switch (in_sizes[i]) {
            case B_ * T_ * D_: E   = (const float*)d_in[i]; break;
            case B_ * T_:      dur = (const int*)  d_in[i]; break;
            case NM * D_:      W   = (const float*)d_in[i]; break;
            case NM:           bmu = (const float*)d_in[i]; break;
            default: break;
        }
    }
    float* out = (float*)d_out;
    const int mu_elems = B_ * NM * MM;          // 20,971,520
    const int write_mask = (out_size >= mu_elems + B_ * MM) ? 1 : 0;

    gemm_scan_kernel<<<dim3(T_ / TT + 1, B_), 256>>>(E, W, bmu, dur);
    upsample_store<<<dim3(MM / 128, B_), 256>>>(out, write_mask);
}

// round 5
// speedup vs baseline: 1.2130x; 1.1616x over previous
#include <cuda_runtime.h>
#include <cstdint>

// Problem constants (fixed by reference)
#define B_  32
#define T_  1024
#define D_  256
#define NM  80
#define MM  8192    // MAX_MEL = T_TEXT * MAX_DUR

// Device scratch (no allocations allowed)
__device__ int   g_idx[B_ * MM];      // frame -> token index (only valid frames written)
__device__ int   g_len[B_];           // valid mel length per batch
__device__ float g_mu [B_ * NM * T_]; // per-token mel projection, layout [b][n][t]

// ---------------------------------------------------------------------------
// K2 (fused): token GEMM + duration scan + mask row.
//   blockIdx.x < 16 : GEMM tile  g_mu[b][n][t] = sum_d W[n][d]*E[b][t][d] + b_mu[n]
//   blockIdx.x ==16 : per-batch warp-shuffle scan of durations -> g_idx/g_len,
//                     then writes the mel_mask float row for this batch.
// GEMM: 64-token tile, 80 mel rows, 256 thr as 16(t)x16(n), thread tile 5n x 4t,
// scalar FFMA (measured at the FFMA issue floor).
// ---------------------------------------------------------------------------
#define TT 64   // token tile
#define KC 64   // k chunk
#define EPAD 68 // sE row stride in floats (16B aligned, low-conflict)

__global__ __launch_bounds__(256) void gemm_scan_kernel(
    const float* __restrict__ E, const float* __restrict__ W,
    const float* __restrict__ bmu, const int* __restrict__ dur,
    float* __restrict__ out, int write_mask) {
    const int b   = blockIdx.y;
    const int tid = threadIdx.x;

    if (blockIdx.x == T_ / TT) {
        // ---- scan branch: 256 threads, 4 durations each ----
        __shared__ int wsum[8];
        __shared__ int sL;
        const int lane = tid & 31;
        const int wid  = tid >> 5;
        int4 d4 = *reinterpret_cast<const int4*>(dur + b * T_ + tid * 4);
        int s = d4.x + d4.y + d4.z + d4.w;
#pragma unroll
        for (int off = 1; off < 32; off <<= 1) {
            int v = __shfl_up_sync(0xffffffffu, s, off);
            if (lane >= off) s += v;
        }
        if (lane == 31) wsum[wid] = s;
        __syncthreads();
        int base = 0;
#pragma unroll
        for (int w = 0; w < 8; ++w) base += (w < wid) ? wsum[w] : 0;
        const int end3  = base + s;         // inclusive cum through elem 4*tid+3
        const int start = end3 - (d4.x + d4.y + d4.z + d4.w);
        const int c0 = start + d4.x;
        const int c1 = c0 + d4.y;
        const int c2 = c1 + d4.z;
        int* ib = g_idx + b * MM;
        const int t0 = tid * 4;
        for (int p = start; p < c0; ++p) ib[p] = t0 + 0;
        for (int p = c0;    p < c1; ++p) ib[p] = t0 + 1;
        for (int p = c1;    p < c2; ++p) ib[p] = t0 + 2;
        for (int p = c2;    p < end3; ++p) ib[p] = t0 + 3;
        if (tid == 255) { g_len[b] = end3; sL = end3; }
        __syncthreads();
        if (write_mask) {
            const int L = sL;
            float* maskb = out + (size_t)B_ * NM * MM + (size_t)b * MM;
#pragma unroll
            for (int i = 0; i < 8; ++i) {
                const int g = (tid + i * 256) * 4;
                float4 m;
                m.x = (g + 0 < L) ? 1.0f : 0.0f;
                m.y = (g + 1 < L) ? 1.0f : 0.0f;
                m.z = (g + 2 < L) ? 1.0f : 0.0f;
                m.w = (g + 3 < L) ? 1.0f : 0.0f;
                *reinterpret_cast<float4*>(maskb + g) = m;
            }
        }
        return;
    }

    // ---- GEMM branch (scalar FFMA, round-1 proven) ----
    const int t0 = blockIdx.x * TT;
    const int tx = tid & 15;   // token dir (4 tokens each)
    const int ty = tid >> 4;   // mel dir   (5 mels each)

    __shared__ float sW[NM * KC];      // [n][k], row stride KC
    __shared__ float sE[KC * EPAD];    // [k][t], row stride EPAD

    float acc[5][4];
#pragma unroll
    for (int i = 0; i < 5; ++i)
#pragma unroll
        for (int j = 0; j < 4; ++j) acc[i][j] = 0.0f;

    for (int kc = 0; kc < D_; kc += KC) {
        for (int q = tid; q < NM * (KC / 4); q += 256) {
            const int n  = q >> 4;          // KC/4 = 16 float4 per row
            const int kf = q & 15;
            float4 v = *reinterpret_cast<const float4*>(W + n * D_ + kc + kf * 4);
            *reinterpret_cast<float4*>(sW + n * KC + kf * 4) = v;
        }
        for (int q = tid; q < TT * (KC / 4); q += 256) {
            const int t  = q >> 4;
            const int kf = q & 15;
            float4 v = *reinterpret_cast<const float4*>(
                E + ((size_t)b * T_ + t0 + t) * D_ + kc + kf * 4);
            const int k = kf * 4;
            sE[(k + 0) * EPAD + t] = v.x;
            sE[(k + 1) * EPAD + t] = v.y;
            sE[(k + 2) * EPAD + t] = v.z;
            sE[(k + 3) * EPAD + t] = v.w;
        }
        __syncthreads();

#pragma unroll 8
        for (int k = 0; k < KC; ++k) {
            float4 e = *reinterpret_cast<const float4*>(&sE[k * EPAD + tx * 4]);
            float w0 = sW[(ty * 5 + 0) * KC + k];
            float w1 = sW[(ty * 5 + 1) * KC + k];
            float w2 = sW[(ty * 5 + 2) * KC + k];
            float w3 = sW[(ty * 5 + 3) * KC + k];
            float w4 = sW[(ty * 5 + 4) * KC + k];
            acc[0][0] += w0 * e.x; acc[0][1] += w0 * e.y; acc[0][2] += w0 * e.z; acc[0][3] += w0 * e.w;
            acc[1][0] += w1 * e.x; acc[1][1] += w1 * e.y; acc[1][2] += w1 * e.z; acc[1][3] += w1 * e.w;
            acc[2][0] += w2 * e.x; acc[2][1] += w2 * e.y; acc[2][2] += w2 * e.z; acc[2][3] += w2 * e.w;
            acc[3][0] += w3 * e.x; acc[3][1] += w3 * e.y; acc[3][2] += w3 * e.z; acc[3][3] += w3 * e.w;
            acc[4][0] += w4 * e.x; acc[4][1] += w4 * e.y; acc[4][2] += w4 * e.z; acc[4][3] += w4 * e.w;
        }
        __syncthreads();
    }

#pragma unroll
    for (int i = 0; i < 5; ++i) {
        const int n = ty * 5 + i;
        const float bv = bmu[n];
        float4 r;
        r.x = acc[i][0] + bv;
        r.y = acc[i][1] + bv;
        r.z = acc[i][2] + bv;
        r.w = acc[i][3] + bv;
        *reinterpret_cast<float4*>(g_mu + ((size_t)b * NM + n) * T_ + t0 + tx * 4) = r;
    }
}

// ---------------------------------------------------------------------------
// K3: scatter per-token mu columns into out[b][n][p].
// Block = (128-frame tile, batch), 256 threads. Thread (n0=tid>>5, g=(tid&31)*4)
// handles rows n0+8j (j=0..9): indices loaded once, 10 independent
// gather->STG.128 chains (high MLP). Mask row handled by the scan branch.
// ---------------------------------------------------------------------------
__global__ __launch_bounds__(256) void upsample_store(float* __restrict__ out) {
    const int b  = blockIdx.y;
    const int f0 = blockIdx.x * 128;
    __shared__ int sidx[128];
    const int L = g_len[b];

    if (threadIdx.x < 128) {
        const int p = f0 + threadIdx.x;
        const int t = g_idx[b * MM + p];
        sidx[threadIdx.x] = (p < L) ? t : -1;   // -1 marks padding frame
    }
    __syncthreads();

    const int n0 = threadIdx.x >> 5;        // 0..7
    const int g  = (threadIdx.x & 31) * 4;  // 0..124
    const int t0 = sidx[g + 0];
    const int t1 = sidx[g + 1];
    const int t2 = sidx[g + 2];
    const int t3 = sidx[g + 3];

    const float* mb = g_mu + (size_t)b * NM * T_;
    float* ob = out + (size_t)b * NM * MM + f0 + g;

#pragma unroll
    for (int j = 0; j < 10; ++j) {
        const int n = n0 + 8 * j;
        const float* r = mb + (size_t)n * T_;
        float4 o;
        o.x = (t0 >= 0) ? __ldg(r + t0) : 0.0f;
        o.y = (t1 >= 0) ? __ldg(r + t1) : 0.0f;
        o.z = (t2 >= 0) ? __ldg(r + t2) : 0.0f;
        o.w = (t3 >= 0) ? __ldg(r + t3) : 0.0f;
        *reinterpret_cast<float4*>(ob + (size_t)n * MM) = o;
    }
}

// ---------------------------------------------------------------------------
extern "C" void kernel_launch(void* const* d_in, const int* in_sizes, int n_in,
                              void* d_out, int out_size) {
    const float* E   = nullptr;
    const int*   dur = nullptr;
    const float* W   = nullptr;
    const float* bmu = nullptr;
    for (int i = 0; i < n_in; ++i) {
        switch (in_sizes[i]) {
            case B_ * T_ * D_: E   = (const float*)d_in[i]; break;
            case B_ * T_:      dur = (const int*)  d_in[i]; break;
            case NM * D_:      W   = (const float*)d_in[i]; break;
            case NM:           bmu = (const float*)d_in[i]; break;
            default: break;
        }
    }
    float* out = (float*)d_out;
    const int mu_elems = B_ * NM * MM;          // 20,971,520
    const int write_mask = (out_size >= mu_elems + B_ * MM) ? 1 : 0;

    gemm_scan_kernel<<<dim3(T_ / TT + 1, B_), 256>>>(E, W, bmu, dur, out, write_mask);
    upsample_store<<<dim3(MM / 128, B_), 256>>>(out);
}

// round 7
// speedup vs baseline: 1.3106x; 1.0804x over previous
#include <cuda_runtime.h>
#include <cstdint>

// Problem constants (fixed by reference)
#define B_  32
#define T_  1024
#define D_  256
#define NM  80
#define MM  8192    // MAX_MEL = T_TEXT * MAX_DUR

#define MT  128     // tokens per CTA tile
#define KC  32      // K chunk
#define NCH (D_/KC) // 8 chunks
#define EP  36      // padded k-stride for E/W tiles (bank = 4*row+col, distinct)
#define CP  132     // padded t-stride for C transpose tile

// Device scratch (no allocations allowed)
__device__ int   g_idx[B_ * MM];
__device__ int   g_len[B_];
__device__ float g_mu [B_ * NM * T_]; // [b][n][t]

// dynamic smem layout (floats)
#define SF_EHI 0                       // 128 x EP
#define SF_ELO (SF_EHI + MT * EP)
#define SF_WHI (SF_ELO + MT * EP)      // 80 x EP
#define SF_WLO (SF_WHI + NM * EP)
#define SF_TOT (SF_WLO + NM * EP)      // 14976 floats = 59904 B
#define SM_TOTAL (SF_TOT * 4)

__device__ __forceinline__ float to_tf32(float a) {
    uint32_t r;
    asm("cvt.rna.tf32.f32 %0, %1;" : "=r"(r) : "f"(a));
    return __uint_as_float(r);
}
__device__ __forceinline__ void mma_tf32(float c[4], const uint32_t a[4],
                                         const uint32_t b[2]) {
    asm volatile(
        "mma.sync.aligned.m16n8k8.row.col.f32.tf32.tf32.f32 "
        "{%0,%1,%2,%3}, {%4,%5,%6,%7}, {%8,%9}, {%0,%1,%2,%3};"
        : "+f"(c[0]), "+f"(c[1]), "+f"(c[2]), "+f"(c[3])
        : "r"(a[0]), "r"(a[1]), "r"(a[2]), "r"(a[3]), "r"(b[0]), "r"(b[1]));
}

// ---------------------------------------------------------------------------
// K2 (fused): TF32 3x-split token GEMM (mma.sync) + duration scan + mask row.
//   blockIdx.x in [0,256): GEMM tile (b = bx>>3, t0 = (bx&7)*128)
//   blockIdx.x in [256,288): scan for batch bx-256
// ---------------------------------------------------------------------------
__global__ __launch_bounds__(256, 2)
void gemm_scan_kernel(const float* __restrict__ E, const float* __restrict__ W,
                      const float* __restrict__ bmu, const int* __restrict__ dur,
                      float* __restrict__ out, int write_mask) {
    extern __shared__ float sm[];
    const int tid = threadIdx.x;

    if (blockIdx.x >= 256) {
        // ---- scan branch ----
        const int b = blockIdx.x - 256;
        int* wsum = reinterpret_cast<int*>(sm);
        int* sLp  = reinterpret_cast<int*>(sm) + 16;
        const int lane = tid & 31;
        const int wid  = tid >> 5;
        int4 d4 = *reinterpret_cast<const int4*>(dur + b * T_ + tid * 4);
        int s = d4.x + d4.y + d4.z + d4.w;
#pragma unroll
        for (int off = 1; off < 32; off <<= 1) {
            int v = __shfl_up_sync(0xffffffffu, s, off);
            if (lane >= off) s += v;
        }
        if (lane == 31) wsum[wid] = s;
        __syncthreads();
        int base = 0;
#pragma unroll
        for (int w = 0; w < 8; ++w) base += (w < wid) ? wsum[w] : 0;
        const int end3  = base + s;
        const int start = end3 - (d4.x + d4.y + d4.z + d4.w);
        const int c0 = start + d4.x;
        const int c1 = c0 + d4.y;
        const int c2 = c1 + d4.z;
        int* ib = g_idx + b * MM;
        const int t0 = tid * 4;
        for (int p = start; p < c0;   ++p) ib[p] = t0 + 0;
        for (int p = c0;    p < c1;   ++p) ib[p] = t0 + 1;
        for (int p = c1;    p < c2;   ++p) ib[p] = t0 + 2;
        for (int p = c2;    p < end3; ++p) ib[p] = t0 + 3;
        if (tid == 255) { g_len[b] = end3; *sLp = end3; }
        __syncthreads();
        if (write_mask) {
            const int L = *sLp;
            float* maskb = out + (size_t)B_ * NM * MM + (size_t)b * MM;
#pragma unroll
            for (int i = 0; i < 8; ++i) {
                const int g = (tid + i * 256) * 4;
                float4 m;
                m.x = (g + 0 < L) ? 1.0f : 0.0f;
                m.y = (g + 1 < L) ? 1.0f : 0.0f;
                m.z = (g + 2 < L) ? 1.0f : 0.0f;
                m.w = (g + 3 < L) ? 1.0f : 0.0f;
                *reinterpret_cast<float4*>(maskb + g) = m;
            }
        }
        return;
    }

    // ---- GEMM branch ----
    const int b    = blockIdx.x >> 3;
    const int t0   = (blockIdx.x & 7) * MT;
    const int wid  = tid >> 5;
    const int lane = tid & 31;
    const int m_base = (wid >> 1) * 32;   // 4 warps over M
    const int n_base = (wid & 1) * 40;    // 2 warps over N

    float*       sEhi = sm + SF_EHI;
    float*       sElo = sm + SF_ELO;
    float*       sWhi = sm + SF_WHI;
    float*       sWlo = sm + SF_WLO;
    const uint32_t* uEhi = reinterpret_cast<const uint32_t*>(sEhi);
    const uint32_t* uElo = reinterpret_cast<const uint32_t*>(sElo);
    const uint32_t* uWhi = reinterpret_cast<const uint32_t*>(sWhi);
    const uint32_t* uWlo = reinterpret_cast<const uint32_t*>(sWlo);

    float acc[2][5][4];
#pragma unroll
    for (int mt = 0; mt < 2; ++mt)
#pragma unroll
        for (int nt = 0; nt < 5; ++nt)
#pragma unroll
            for (int j = 0; j < 4; ++j) acc[mt][nt][j] = 0.0f;

    const int ar = lane >> 2;   // fragment row within 8
    const int ac = lane & 3;    // fragment col within 4

    for (int ch = 0; ch < NCH; ++ch) {
        const int kc = ch * KC;
        // stage E chunk: 128 rows x 8 float4, hi/lo tf32 split
        for (int q = tid; q < MT * (KC / 4); q += 256) {
            const int r  = q >> 3;
            const int kf = q & 7;
            float4 v = *reinterpret_cast<const float4*>(
                E + ((size_t)b * T_ + t0 + r) * D_ + kc + kf * 4);
            float4 hi, lo;
            hi.x = to_tf32(v.x); lo.x = to_tf32(v.x - hi.x);
            hi.y = to_tf32(v.y); lo.y = to_tf32(v.y - hi.y);
            hi.z = to_tf32(v.z); lo.z = to_tf32(v.z - hi.z);
            hi.w = to_tf32(v.w); lo.w = to_tf32(v.w - hi.w);
            *reinterpret_cast<float4*>(sEhi + r * EP + kf * 4) = hi;
            *reinterpret_cast<float4*>(sElo + r * EP + kf * 4) = lo;
        }
        // stage W chunk: 80 rows x 8 float4
        for (int q = tid; q < NM * (KC / 4); q += 256) {
            const int n  = q >> 3;
            const int kf = q & 7;
            float4 v = *reinterpret_cast<const float4*>(W + n * D_ + kc + kf * 4);
            float4 hi, lo;
            hi.x = to_tf32(v.x); lo.x = to_tf32(v.x - hi.x);
            hi.y = to_tf32(v.y); lo.y = to_tf32(v.y - hi.y);
            hi.z = to_tf32(v.z); lo.z = to_tf32(v.z - hi.z);
            hi.w = to_tf32(v.w); lo.w = to_tf32(v.w - hi.w);
            *reinterpret_cast<float4*>(sWhi + n * EP + kf * 4) = hi;
            *reinterpret_cast<float4*>(sWlo + n * EP + kf * 4) = lo;
        }
        __syncthreads();

#pragma unroll
        for (int ks = 0; ks < KC / 8; ++ks) {
            const int k0 = ks * 8;
            // B fragments for all 5 n-tiles
            uint32_t bhi[5][2], blo[5][2];
#pragma unroll
            for (int nt = 0; nt < 5; ++nt) {
                const int rB = (n_base + nt * 8 + ar) * EP + k0 + ac;
                bhi[nt][0] = uWhi[rB];
                bhi[nt][1] = uWhi[rB + 4];
                blo[nt][0] = uWlo[rB];
                blo[nt][1] = uWlo[rB + 4];
            }
#pragma unroll
            for (int mt = 0; mt < 2; ++mt) {
                const int rA = (m_base + mt * 16 + ar) * EP + k0 + ac;
                uint32_t ahi[4], alo[4];
                ahi[0] = uEhi[rA];
                ahi[1] = uEhi[rA + 8 * EP];
                ahi[2] = uEhi[rA + 4];
                ahi[3] = uEhi[rA + 8 * EP + 4];
                alo[0] = uElo[rA];
                alo[1] = uElo[rA + 8 * EP];
                alo[2] = uElo[rA + 4];
                alo[3] = uElo[rA + 8 * EP + 4];
#pragma unroll
                for (int nt = 0; nt < 5; ++nt) {
                    mma_tf32(acc[mt][nt], ahi, bhi[nt]);
                    mma_tf32(acc[mt][nt], ahi, blo[nt]);
                    mma_tf32(acc[mt][nt], alo, bhi[nt]);
                }
            }
        }
        __syncthreads();
    }

    // Epilogue: C frags -> smem [n][t] transpose -> coalesced stores + bias
    float* sC = sm;   // 80 x CP floats (42240 B <= SM_TOTAL)
#pragma unroll
    for (int mt = 0; mt < 2; ++mt) {
        const int row = m_base + mt * 16 + ar;
#pragma unroll
        for (int nt = 0; nt < 5; ++nt) {
            const int col = n_base + nt * 8 + 2 * ac;
            sC[(col + 0) * CP + row]     = acc[mt][nt][0];
            sC[(col + 1) * CP + row]     = acc[mt][nt][1];
            sC[(col + 0) * CP + row + 8] = acc[mt][nt][2];
            sC[(col + 1) * CP + row + 8] = acc[mt][nt][3];
        }
    }
    __syncthreads();

    for (int q = tid; q < NM * (MT / 4); q += 256) {
        const int n = q >> 5;           // MT/4 = 32 float4 per row
        const int f = q & 31;
        const float bv = __ldg(bmu + n);
        float4 v = *reinterpret_cast<const float4*>(sC + n * CP + f * 4);
        v.x += bv; v.y += bv; v.z += bv; v.w += bv;
        *reinterpret_cast<float4*>(g_mu + ((size_t)b * NM + n) * T_ + t0 + f * 4) = v;
    }
}

// ---------------------------------------------------------------------------
// K3: scatter per-token mu columns into out[b][n][p] (proven).
// ---------------------------------------------------------------------------
__global__ __launch_bounds__(256) void upsample_store(float* __restrict__ out) {
    const int b  = blockIdx.y;
    const int f0 = blockIdx.x * 128;
    __shared__ int sidx[128];
    const int L = g_len[b];

    if (threadIdx.x < 128) {
        const int p = f0 + threadIdx.x;
        const int t = g_idx[b * MM + p];
        sidx[threadIdx.x] = (p < L) ? t : -1;
    }
    __syncthreads();

    const int n0 = threadIdx.x >> 5;
    const int g  = (threadIdx.x & 31) * 4;
    const int t0 = sidx[g + 0];
    const int t1 = sidx[g + 1];
    const int t2 = sidx[g + 2];
    const int t3 = sidx[g + 3];

    const float* mb = g_mu + (size_t)b * NM * T_;
    float* ob = out + (size_t)b * NM * MM + f0 + g;

#pragma unroll
    for (int j = 0; j < 10; ++j) {
        const int n = n0 + 8 * j;
        const float* r = mb + (size_t)n * T_;
        float4 o;
        o.x = (t0 >= 0) ? __ldg(r + t0) : 0.0f;
        o.y = (t1 >= 0) ? __ldg(r + t1) : 0.0f;
        o.z = (t2 >= 0) ? __ldg(r + t2) : 0.0f;
        o.w = (t3 >= 0) ? __ldg(r + t3) : 0.0f;
        *reinterpret_cast<float4*>(ob + (size_t)n * MM) = o;
    }
}

// ---------------------------------------------------------------------------
extern "C" void kernel_launch(void* const* d_in, const int* in_sizes, int n_in,
                              void* d_out, int out_size) {
    const float* E   = nullptr;
    const int*   dur = nullptr;
    const float* W   = nullptr;
    const float* bmu = nullptr;
    for (int i = 0; i < n_in; ++i) {
        switch (in_sizes[i]) {
            case B_ * T_ * D_: E   = (const float*)d_in[i]; break;
            case B_ * T_:      dur = (const int*)  d_in[i]; break;
            case NM * D_:      W   = (const float*)d_in[i]; break;
            case NM:           bmu = (const float*)d_in[i]; break;
            default: break;
        }
    }
    float* out = (float*)d_out;
    const int mu_elems = B_ * NM * MM;
    const int write_mask = (out_size >= mu_elems + B_ * MM) ? 1 : 0;

    cudaFuncSetAttribute(gemm_scan_kernel,
                         cudaFuncAttributeMaxDynamicSharedMemorySize, SM_TOTAL);

    gemm_scan_kernel<<<288, 256, SM_TOTAL>>>(E, W, bmu, dur, out, write_mask);
    upsample_store<<<dim3(MM / 128, B_), 256>>>(out);
}

// round 8
// speedup vs baseline: 1.4483x; 1.1051x over previous
#include <cuda_runtime.h>
#include <cstdint>

// Problem constants (fixed by reference)
#define B_  32
#define T_  1024
#define D_  256
#define NM  80
#define MM  8192    // MAX_MEL = T_TEXT * MAX_DUR

#define MT  128     // tokens per CTA tile
#define KC  32      // K chunk
#define NCH (D_/KC) // 8 chunks
#define KP  20      // stride of staged tiles in u32 (bf16x2) units; conflict-free
#define CP  132     // padded t-stride for C transpose tile

// Device scratch (no allocations allowed)
__device__ int   g_idx[B_ * MM];
__device__ int   g_len[B_];
__device__ float g_mu [B_ * NM * T_]; // [b][n][t]

// dynamic smem layout (u32 units)
#define SU_EHI 0                        // 128 x KP
#define SU_ELO (SU_EHI + MT * KP)
#define SU_WHI (SU_ELO + MT * KP)       // 80 x KP
#define SU_WLO (SU_WHI + NM * KP)
#define SU_TOT (SU_WLO + NM * KP)       // 8320 u32 = 33280 B
// epilogue needs 80*CP floats = 42240 B
#define SM_TOTAL (NM * CP * 4)

// pack two floats' bf16-truncations: low16 = ax[31:16], high16 = ay[31:16]
__device__ __forceinline__ uint32_t hi_pair(float ax, float ay) {
    return __byte_perm(__float_as_uint(ax), __float_as_uint(ay), 0x7632);
}
__device__ __forceinline__ float hi_of(float a) {
    return __uint_as_float(__float_as_uint(a) & 0xFFFF0000u);
}
__device__ __forceinline__ uint32_t lo_pair(float lx, float ly) {
    uint32_t r;  // d.lo = cvt(%2), d.hi = cvt(%1)
    asm("cvt.rn.bf16x2.f32 %0, %1, %2;" : "=r"(r) : "f"(ly), "f"(lx));
    return r;
}
__device__ __forceinline__ void mma_bf16(float c[4], const uint32_t a[4],
                                         const uint32_t b[2]) {
    asm volatile(
        "mma.sync.aligned.m16n8k16.row.col.f32.bf16.bf16.f32 "
        "{%0,%1,%2,%3}, {%4,%5,%6,%7}, {%8,%9}, {%0,%1,%2,%3};"
        : "+f"(c[0]), "+f"(c[1]), "+f"(c[2]), "+f"(c[3])
        : "r"(a[0]), "r"(a[1]), "r"(a[2]), "r"(a[3]), "r"(b[0]), "r"(b[1]));
}

// ---------------------------------------------------------------------------
// K2 (fused): bf16 3-product split token GEMM (mma.sync.m16n8k16)
//             + duration scan + mask row.
//   blockIdx.x in [0,256): GEMM tile (b = bx>>3, t0 = (bx&7)*128)
//   blockIdx.x in [256,288): scan for batch bx-256
// ---------------------------------------------------------------------------
__global__ __launch_bounds__(256, 2)
void gemm_scan_kernel(const float* __restrict__ E, const float* __restrict__ W,
                      const float* __restrict__ bmu, const int* __restrict__ dur,
                      float* __restrict__ out, int write_mask) {
    extern __shared__ float sm[];
    uint32_t* su = reinterpret_cast<uint32_t*>(sm);
    const int tid = threadIdx.x;

    if (blockIdx.x >= 256) {
        // ---- scan branch ----
        const int b = blockIdx.x - 256;
        int* wsum = reinterpret_cast<int*>(sm);
        int* sLp  = reinterpret_cast<int*>(sm) + 16;
        const int lane = tid & 31;
        const int wid  = tid >> 5;
        int4 d4 = *reinterpret_cast<const int4*>(dur + b * T_ + tid * 4);
        int s = d4.x + d4.y + d4.z + d4.w;
#pragma unroll
        for (int off = 1; off < 32; off <<= 1) {
            int v = __shfl_up_sync(0xffffffffu, s, off);
            if (lane >= off) s += v;
        }
        if (lane == 31) wsum[wid] = s;
        __syncthreads();
        int base = 0;
#pragma unroll
        for (int w = 0; w < 8; ++w) base += (w < wid) ? wsum[w] : 0;
        const int end3  = base + s;
        const int start = end3 - (d4.x + d4.y + d4.z + d4.w);
        const int c0 = start + d4.x;
        const int c1 = c0 + d4.y;
        const int c2 = c1 + d4.z;
        int* ib = g_idx + b * MM;
        const int t0 = tid * 4;
        for (int p = start; p < c0;   ++p) ib[p] = t0 + 0;
        for (int p = c0;    p < c1;   ++p) ib[p] = t0 + 1;
        for (int p = c1;    p < c2;   ++p) ib[p] = t0 + 2;
        for (int p = c2;    p < end3; ++p) ib[p] = t0 + 3;
        if (tid == 255) { g_len[b] = end3; *sLp = end3; }
        __syncthreads();
        if (write_mask) {
            const int L = *sLp;
            float* maskb = out + (size_t)B_ * NM * MM + (size_t)b * MM;
#pragma unroll
            for (int i = 0; i < 8; ++i) {
                const int g = (tid + i * 256) * 4;
                float4 m;
                m.x = (g + 0 < L) ? 1.0f : 0.0f;
                m.y = (g + 1 < L) ? 1.0f : 0.0f;
                m.z = (g + 2 < L) ? 1.0f : 0.0f;
                m.w = (g + 3 < L) ? 1.0f : 0.0f;
                *reinterpret_cast<float4*>(maskb + g) = m;
            }
        }
        return;
    }

    // ---- GEMM branch ----
    const int b    = blockIdx.x >> 3;
    const int t0   = (blockIdx.x & 7) * MT;
    const int wid  = tid >> 5;
    const int lane = tid & 31;
    const int m_base = (wid >> 1) * 32;   // 4 warps over M
    const int n_base = (wid & 1) * 40;    // 2 warps over N
    const int gr = lane >> 2;             // fragment group row
    const int tg = lane & 3;              // thread-in-group

    uint32_t* uEhi = su + SU_EHI;
    uint32_t* uElo = su + SU_ELO;
    uint32_t* uWhi = su + SU_WHI;
    uint32_t* uWlo = su + SU_WLO;

    float acc[2][5][4];
#pragma unroll
    for (int mt = 0; mt < 2; ++mt)
#pragma unroll
        for (int nt = 0; nt < 5; ++nt)
#pragma unroll
            for (int j = 0; j < 4; ++j) acc[mt][nt][j] = 0.0f;

    for (int ch = 0; ch < NCH; ++ch) {
        const int kc = ch * KC;
        // stage E chunk: 128 rows x 8 float4 -> bf16 hi/lo pairs
        for (int q = tid; q < MT * (KC / 4); q += 256) {
            const int r  = q >> 3;
            const int kf = q & 7;
            float4 v = *reinterpret_cast<const float4*>(
                E + ((size_t)b * T_ + t0 + r) * D_ + kc + kf * 4);
            const float hx = hi_of(v.x), hy = hi_of(v.y);
            const float hz = hi_of(v.z), hw = hi_of(v.w);
            uint2 hp, lp;
            hp.x = hi_pair(v.x, v.y);
            hp.y = hi_pair(v.z, v.w);
            lp.x = lo_pair(v.x - hx, v.y - hy);
            lp.y = lo_pair(v.z - hz, v.w - hw);
            *reinterpret_cast<uint2*>(uEhi + r * KP + kf * 2) = hp;
            *reinterpret_cast<uint2*>(uElo + r * KP + kf * 2) = lp;
        }
        // stage W chunk: 80 rows x 8 float4
        for (int q = tid; q < NM * (KC / 4); q += 256) {
            const int n  = q >> 3;
            const int kf = q & 7;
            float4 v = *reinterpret_cast<const float4*>(W + n * D_ + kc + kf * 4);
            const float hx = hi_of(v.x), hy = hi_of(v.y);
            const float hz = hi_of(v.z), hw = hi_of(v.w);
            uint2 hp, lp;
            hp.x = hi_pair(v.x, v.y);
            hp.y = hi_pair(v.z, v.w);
            lp.x = lo_pair(v.x - hx, v.y - hy);
            lp.y = lo_pair(v.z - hz, v.w - hw);
            *reinterpret_cast<uint2*>(uWhi + n * KP + kf * 2) = hp;
            *reinterpret_cast<uint2*>(uWlo + n * KP + kf * 2) = lp;
        }
        __syncthreads();

#pragma unroll
        for (int ks = 0; ks < KC / 16; ++ks) {
            const int kp0 = ks * 8;
            // B fragments (hi/lo) for 5 n-tiles: b0 at kp0+tg, b1 at kp0+4+tg
            uint32_t bhi[5][2], blo[5][2];
#pragma unroll
            for (int nt = 0; nt < 5; ++nt) {
                const int rB = (n_base + nt * 8 + gr) * KP + kp0 + tg;
                bhi[nt][0] = uWhi[rB];
                bhi[nt][1] = uWhi[rB + 4];
                blo[nt][0] = uWlo[rB];
                blo[nt][1] = uWlo[rB + 4];
            }
#pragma unroll
            for (int mt = 0; mt < 2; ++mt) {
                const int rA = (m_base + mt * 16 + gr) * KP + kp0 + tg;
                uint32_t ahi[4], alo[4];
                ahi[0] = uEhi[rA];
                ahi[1] = uEhi[rA + 8 * KP];
                ahi[2] = uEhi[rA + 4];
                ahi[3] = uEhi[rA + 8 * KP + 4];
                alo[0] = uElo[rA];
                alo[1] = uElo[rA + 8 * KP];
                alo[2] = uElo[rA + 4];
                alo[3] = uElo[rA + 8 * KP + 4];
#pragma unroll
                for (int nt = 0; nt < 5; ++nt) {
                    mma_bf16(acc[mt][nt], ahi, bhi[nt]);
                    mma_bf16(acc[mt][nt], ahi, blo[nt]);
                    mma_bf16(acc[mt][nt], alo, bhi[nt]);
                }
            }
        }
        __syncthreads();
    }

    // Epilogue: C frags -> smem [n][t] transpose -> coalesced stores + bias
    float* sC = sm;   // 80 x CP floats
#pragma unroll
    for (int mt = 0; mt < 2; ++mt) {
        const int row = m_base + mt * 16 + gr;
#pragma unroll
        for (int nt = 0; nt < 5; ++nt) {
            const int col = n_base + nt * 8 + 2 * tg;
            sC[(col + 0) * CP + row]     = acc[mt][nt][0];
            sC[(col + 1) * CP + row]     = acc[mt][nt][1];
            sC[(col + 0) * CP + row + 8] = acc[mt][nt][2];
            sC[(col + 1) * CP + row + 8] = acc[mt][nt][3];
        }
    }
    __syncthreads();

    for (int q = tid; q < NM * (MT / 4); q += 256) {
        const int n = q >> 5;           // MT/4 = 32 float4 per row
        const int f = q & 31;
        const float bv = __ldg(bmu + n);
        float4 v = *reinterpret_cast<const float4*>(sC + n * CP + f * 4);
        v.x += bv; v.y += bv; v.z += bv; v.w += bv;
        *reinterpret_cast<float4*>(g_mu + ((size_t)b * NM + n) * T_ + t0 + f * 4) = v;
    }
}

// ---------------------------------------------------------------------------
// K3: scatter per-token mu columns into out[b][n][p] (proven).
// ---------------------------------------------------------------------------
__global__ __launch_bounds__(256) void upsample_store(float* __restrict__ out) {
    const int b  = blockIdx.y;
    const int f0 = blockIdx.x * 128;
    __shared__ int sidx[128];
    const int L = g_len[b];

    if (threadIdx.x < 128) {
        const int p = f0 + threadIdx.x;
        const int t = g_idx[b * MM + p];
        sidx[threadIdx.x] = (p < L) ? t : -1;
    }
    __syncthreads();

    const int n0 = threadIdx.x >> 5;
    const int g  = (threadIdx.x & 31) * 4;
    const int t0 = sidx[g + 0];
    const int t1 = sidx[g + 1];
    const int t2 = sidx[g + 2];
    const int t3 = sidx[g + 3];

    const float* mb = g_mu + (size_t)b * NM * T_;
    float* ob = out + (size_t)b * NM * MM + f0 + g;

#pragma unroll
    for (int j = 0; j < 10; ++j) {
        const int n = n0 + 8 * j;
        const float* r = mb + (size_t)n * T_;
        float4 o;
        o.x = (t0 >= 0) ? __ldg(r + t0) : 0.0f;
        o.y = (t1 >= 0) ? __ldg(r + t1) : 0.0f;
        o.z = (t2 >= 0) ? __ldg(r + t2) : 0.0f;
        o.w = (t3 >= 0) ? __ldg(r + t3) : 0.0f;
        *reinterpret_cast<float4*>(ob + (size_t)n * MM) = o;
    }
}

// ---------------------------------------------------------------------------
extern "C" void kernel_launch(void* const* d_in, const int* in_sizes, int n_in,
                              void* d_out, int out_size) {
    const float* E   = nullptr;
    const int*   dur = nullptr;
    const float* W   = nullptr;
    const float* bmu = nullptr;
    for (int i = 0; i < n_in; ++i) {
        switch (in_sizes[i]) {
            case B_ * T_ * D_: E   = (const float*)d_in[i]; break;
            case B_ * T_:      dur = (const int*)  d_in[i]; break;
            case NM * D_:      W   = (const float*)d_in[i]; break;
            case NM:           bmu = (const float*)d_in[i]; break;
            default: break;
        }
    }
    float* out = (float*)d_out;
    const int mu_elems = B_ * NM * MM;
    const int write_mask = (out_size >= mu_elems + B_ * MM) ? 1 : 0;

    cudaFuncSetAttribute(gemm_scan_kernel,
                         cudaFuncAttributeMaxDynamicSharedMemorySize, SM_TOTAL);

    gemm_scan_kernel<<<288, 256, SM_TOTAL>>>(E, W, bmu, dur, out, write_mask);
    upsample_store<<<dim3(MM / 128, B_), 256>>>(out);
}

// round 9
// speedup vs baseline: 1.7500x; 1.2083x over previous
#include <cuda_runtime.h>
#include <cstdint>

// Problem constants (fixed by reference)
#define B_  32
#define T_  1024
#define D_  256
#define NM  80
#define MM  8192    // MAX_MEL = T_TEXT * MAX_DUR

#define MT  128     // tokens per CTA tile
#define KC  32      // K chunk
#define NCH (D_/KC) // 8 chunks
#define KP  20      // stride of staged tiles in u32 (bf16x2) units; conflict-free
#define CP  132     // padded t-stride for C transpose tile

// Block ranges in the fused grid
#define NB_SCAN  32
#define NB_GEMM  256
#define NB_SCAT  2048
#define GRID_TOT (NB_SCAN + NB_GEMM + NB_SCAT)

// Device scratch (no allocations allowed)
__device__ int   g_idx[B_ * MM];
__device__ int   g_len[B_];
__device__ float g_mu [B_ * NM * T_]; // [b][n][t]
__device__ int   g_done[B_];          // per-batch completion counters (scan+8 gemm)

// dynamic smem layout (u32 units)
#define SU_EHI 0                        // 128 x KP
#define SU_ELO (SU_EHI + MT * KP)
#define SU_WHI (SU_ELO + MT * KP)       // 80 x KP
#define SU_WLO (SU_WHI + NM * KP)
#define SU_TOT (SU_WLO + NM * KP)       // 8320 u32 = 33280 B
#define SM_TOTAL (NM * CP * 4)          // 42240 B (epilogue transpose tile)

// pack two floats' bf16-truncations
__device__ __forceinline__ uint32_t hi_pair(float ax, float ay) {
    return __byte_perm(__float_as_uint(ax), __float_as_uint(ay), 0x7632);
}
__device__ __forceinline__ float hi_of(float a) {
    return __uint_as_float(__float_as_uint(a) & 0xFFFF0000u);
}
__device__ __forceinline__ uint32_t lo_pair(float lx, float ly) {
    uint32_t r;
    asm("cvt.rn.bf16x2.f32 %0, %1, %2;" : "=r"(r) : "f"(ly), "f"(lx));
    return r;
}
__device__ __forceinline__ void mma_bf16(float c[4], const uint32_t a[4],
                                         const uint32_t b[2]) {
    asm volatile(
        "mma.sync.aligned.m16n8k16.row.col.f32.bf16.bf16.f32 "
        "{%0,%1,%2,%3}, {%4,%5,%6,%7}, {%8,%9}, {%0,%1,%2,%3};"
        : "+f"(c[0]), "+f"(c[1]), "+f"(c[2]), "+f"(c[3])
        : "r"(a[0]), "r"(a[1]), "r"(a[2]), "r"(a[3]), "r"(b[0]), "r"(b[1]));
}
__device__ __forceinline__ int ld_acquire(const int* p) {
    int v;
    asm volatile("ld.acquire.gpu.global.s32 %0, [%1];" : "=r"(v) : "l"(p) : "memory");
    return v;
}

__global__ void zero_flags() {
    if (threadIdx.x < B_) g_done[threadIdx.x] = 0;
}

// ---------------------------------------------------------------------------
// Fused kernel: scan [0,32) | gemm [32,288) | scatter [288,2336)
// ---------------------------------------------------------------------------
__global__ __launch_bounds__(256)
void fused_kernel(const float* __restrict__ E, const float* __restrict__ W,
                  const float* __restrict__ bmu, const int* __restrict__ dur,
                  float* __restrict__ out, int write_mask) {
    extern __shared__ float sm[];
    uint32_t* su = reinterpret_cast<uint32_t*>(sm);
    const int tid = threadIdx.x;
    const int bx  = blockIdx.x;

    if (bx < NB_SCAN) {
        // ================= scan branch =================
        const int b = bx;
        int* wsum = reinterpret_cast<int*>(sm);
        int* sLp  = reinterpret_cast<int*>(sm) + 16;
        const int lane = tid & 31;
        const int wid  = tid >> 5;
        int4 d4 = *reinterpret_cast<const int4*>(dur + b * T_ + tid * 4);
        int s = d4.x + d4.y + d4.z + d4.w;
#pragma unroll
        for (int off = 1; off < 32; off <<= 1) {
            int v = __shfl_up_sync(0xffffffffu, s, off);
            if (lane >= off) s += v;
        }
        if (lane == 31) wsum[wid] = s;
        __syncthreads();
        int base = 0;
#pragma unroll
        for (int w = 0; w < 8; ++w) base += (w < wid) ? wsum[w] : 0;
        const int end3  = base + s;
        const int start = end3 - (d4.x + d4.y + d4.z + d4.w);
        const int c0 = start + d4.x;
        const int c1 = c0 + d4.y;
        const int c2 = c1 + d4.z;
        int* ib = g_idx + b * MM;
        const int t0 = tid * 4;
        for (int p = start; p < c0;   ++p) ib[p] = t0 + 0;
        for (int p = c0;    p < c1;   ++p) ib[p] = t0 + 1;
        for (int p = c1;    p < c2;   ++p) ib[p] = t0 + 2;
        for (int p = c2;    p < end3; ++p) ib[p] = t0 + 3;
        if (tid == 255) { g_len[b] = end3; *sLp = end3; }
        __syncthreads();
        if (write_mask) {
            const int L = *sLp;
            float* maskb = out + (size_t)B_ * NM * MM + (size_t)b * MM;
#pragma unroll
            for (int i = 0; i < 8; ++i) {
                const int g = (tid + i * 256) * 4;
                float4 m;
                m.x = (g + 0 < L) ? 1.0f : 0.0f;
                m.y = (g + 1 < L) ? 1.0f : 0.0f;
                m.z = (g + 2 < L) ? 1.0f : 0.0f;
                m.w = (g + 3 < L) ? 1.0f : 0.0f;
                *reinterpret_cast<float4*>(maskb + g) = m;
            }
        }
        __threadfence();
        __syncthreads();
        if (tid == 0) atomicAdd(&g_done[b], 1);
        return;
    }

    if (bx < NB_SCAN + NB_GEMM) {
        // ================= GEMM branch =================
        const int gb   = bx - NB_SCAN;
        const int b    = gb >> 3;
        const int t0   = (gb & 7) * MT;
        const int wid  = tid >> 5;
        const int lane = tid & 31;
        const int m_base = (wid >> 1) * 32;
        const int n_base = (wid & 1) * 40;
        const int gr = lane >> 2;
        const int tg = lane & 3;

        uint32_t* uEhi = su + SU_EHI;
        uint32_t* uElo = su + SU_ELO;
        uint32_t* uWhi = su + SU_WHI;
        uint32_t* uWlo = su + SU_WLO;

        float acc[2][5][4];
#pragma unroll
        for (int mt = 0; mt < 2; ++mt)
#pragma unroll
            for (int nt = 0; nt < 5; ++nt)
#pragma unroll
                for (int j = 0; j < 4; ++j) acc[mt][nt][j] = 0.0f;

        // register prefetch buffers
        float4 eR[4];
        float4 wR[3];
        const float* Eb = E + ((size_t)b * T_ + t0) * D_;

        // prefetch chunk 0
        {
#pragma unroll
            for (int i = 0; i < 4; ++i) {
                const int q = tid + i * 256;
                eR[i] = *reinterpret_cast<const float4*>(Eb + (size_t)(q >> 3) * D_ + (q & 7) * 4);
            }
#pragma unroll
            for (int i = 0; i < 3; ++i) {
                const int q = tid + i * 256;
                if (q < NM * 8)
                    wR[i] = *reinterpret_cast<const float4*>(W + (q >> 3) * D_ + (q & 7) * 4);
            }
        }

        for (int ch = 0; ch < NCH; ++ch) {
            __syncthreads();   // smem free (MMA of previous chunk done)
            // store staged chunk from regs (convert to bf16 hi/lo pairs)
#pragma unroll
            for (int i = 0; i < 4; ++i) {
                const int q = tid + i * 256;
                const int r = q >> 3, kf = q & 7;
                float4 v = eR[i];
                uint2 hp, lp;
                hp.x = hi_pair(v.x, v.y);
                hp.y = hi_pair(v.z, v.w);
                lp.x = lo_pair(v.x - hi_of(v.x), v.y - hi_of(v.y));
                lp.y = lo_pair(v.z - hi_of(v.z), v.w - hi_of(v.w));
                *reinterpret_cast<uint2*>(uEhi + r * KP + kf * 2) = hp;
                *reinterpret_cast<uint2*>(uElo + r * KP + kf * 2) = lp;
            }
#pragma unroll
            for (int i = 0; i < 3; ++i) {
                const int q = tid + i * 256;
                if (q < NM * 8) {
                    const int n = q >> 3, kf = q & 7;
                    float4 v = wR[i];
                    uint2 hp, lp;
                    hp.x = hi_pair(v.x, v.y);
                    hp.y = hi_pair(v.z, v.w);
                    lp.x = lo_pair(v.x - hi_of(v.x), v.y - hi_of(v.y));
                    lp.y = lo_pair(v.z - hi_of(v.z), v.w - hi_of(v.w));
                    *reinterpret_cast<uint2*>(uWhi + n * KP + kf * 2) = hp;
                    *reinterpret_cast<uint2*>(uWlo + n * KP + kf * 2) = lp;
                }
            }
            __syncthreads();
            // issue prefetch of next chunk (latency hidden behind MMAs)
            if (ch + 1 < NCH) {
                const int kc = (ch + 1) * KC;
#pragma unroll
                for (int i = 0; i < 4; ++i) {
                    const int q = tid + i * 256;
                    eR[i] = *reinterpret_cast<const float4*>(
                        Eb + (size_t)(q >> 3) * D_ + kc + (q & 7) * 4);
                }
#pragma unroll
                for (int i = 0; i < 3; ++i) {
                    const int q = tid + i * 256;
                    if (q < NM * 8)
                        wR[i] = *reinterpret_cast<const float4*>(
                            W + (q >> 3) * D_ + kc + (q & 7) * 4);
                }
            }

#pragma unroll
            for (int ks = 0; ks < KC / 16; ++ks) {
                const int kp0 = ks * 8;
                uint32_t bhi[5][2], blo[5][2];
#pragma unroll
                for (int nt = 0; nt < 5; ++nt) {
                    const int rB = (n_base + nt * 8 + gr) * KP + kp0 + tg;
                    bhi[nt][0] = uWhi[rB];
                    bhi[nt][1] = uWhi[rB + 4];
                    blo[nt][0] = uWlo[rB];
                    blo[nt][1] = uWlo[rB + 4];
                }
#pragma unroll
                for (int mt = 0; mt < 2; ++mt) {
                    const int rA = (m_base + mt * 16 + gr) * KP + kp0 + tg;
                    uint32_t ahi[4], alo[4];
                    ahi[0] = uEhi[rA];
                    ahi[1] = uEhi[rA + 8 * KP];
                    ahi[2] = uEhi[rA + 4];
                    ahi[3] = uEhi[rA + 8 * KP + 4];
                    alo[0] = uElo[rA];
                    alo[1] = uElo[rA + 8 * KP];
                    alo[2] = uElo[rA + 4];
                    alo[3] = uElo[rA + 8 * KP + 4];
#pragma unroll
                    for (int nt = 0; nt < 5; ++nt) {
                        mma_bf16(acc[mt][nt], ahi, bhi[nt]);
                        mma_bf16(acc[mt][nt], ahi, blo[nt]);
                        mma_bf16(acc[mt][nt], alo, bhi[nt]);
                    }
                }
            }
        }
        __syncthreads();

        // Epilogue: C frags -> smem [n][t] transpose -> coalesced stores + bias
        float* sC = sm;
#pragma unroll
        for (int mt = 0; mt < 2; ++mt) {
            const int row = m_base + mt * 16 + gr;
#pragma unroll
            for (int nt = 0; nt < 5; ++nt) {
                const int col = n_base + nt * 8 + 2 * tg;
                sC[(col + 0) * CP + row]     = acc[mt][nt][0];
                sC[(col + 1) * CP + row]     = acc[mt][nt][1];
                sC[(col + 0) * CP + row + 8] = acc[mt][nt][2];
                sC[(col + 1) * CP + row + 8] = acc[mt][nt][3];
            }
        }
        __syncthreads();

        for (int q = tid; q < NM * (MT / 4); q += 256) {
            const int n = q >> 5;
            const int f = q & 31;
            const float bv = __ldg(bmu + n);
            float4 v = *reinterpret_cast<const float4*>(sC + n * CP + f * 4);
            v.x += bv; v.y += bv; v.z += bv; v.w += bv;
            *reinterpret_cast<float4*>(g_mu + ((size_t)b * NM + n) * T_ + t0 + f * 4) = v;
        }
        __threadfence();
        __syncthreads();
        if (tid == 0) atomicAdd(&g_done[b], 1);
        return;
    }

    // ================= scatter branch =================
    {
        const int id = bx - (NB_SCAN + NB_GEMM);
        const int b  = id >> 6;            // batch-major: aligns with producer order
        const int f0 = (id & 63) * 128;

        // wait for this batch's scan + all 8 gemm tiles
        if (tid == 0) {
            while (ld_acquire(&g_done[b]) < 9) __nanosleep(256);
        }
        __syncthreads();
        __threadfence();

        __shared__ int sidx[128];
        const int L = g_len[b];
        if (tid < 128) {
            const int p = f0 + tid;
            const int t = g_idx[b * MM + p];
            sidx[tid] = (p < L) ? t : -1;
        }
        __syncthreads();

        const int n0 = tid >> 5;
        const int g  = (tid & 31) * 4;
        const int t0 = sidx[g + 0];
        const int t1 = sidx[g + 1];
        const int t2 = sidx[g + 2];
        const int t3 = sidx[g + 3];

        const float* mb = g_mu + (size_t)b * NM * T_;
        float* ob = out + (size_t)b * NM * MM + f0 + g;

#pragma unroll
        for (int j = 0; j < 10; ++j) {
            const int n = n0 + 8 * j;
            const float* r = mb + (size_t)n * T_;
            float4 o;
            o.x = (t0 >= 0) ? __ldg(r + t0) : 0.0f;
            o.y = (t1 >= 0) ? __ldg(r + t1) : 0.0f;
            o.z = (t2 >= 0) ? __ldg(r + t2) : 0.0f;
            o.w = (t3 >= 0) ? __ldg(r + t3) : 0.0f;
            *reinterpret_cast<float4*>(ob + (size_t)n * MM) = o;
        }
    }
}

// ---------------------------------------------------------------------------
extern "C" void kernel_launch(void* const* d_in, const int* in_sizes, int n_in,
                              void* d_out, int out_size) {
    const float* E   = nullptr;
    const int*   dur = nullptr;
    const float* W   = nullptr;
    const float* bmu = nullptr;
    for (int i = 0; i < n_in; ++i) {
        switch (in_sizes[i]) {
            case B_ * T_ * D_: E   = (const float*)d_in[i]; break;
            case B_ * T_:      dur = (const int*)  d_in[i]; break;
            case NM * D_:      W   = (const float*)d_in[i]; break;
            case NM:           bmu = (const float*)d_in[i]; break;
            default: break;
        }
    }
    float* out = (float*)d_out;
    const int mu_elems = B_ * NM * MM;
    const int write_mask = (out_size >= mu_elems + B_ * MM) ? 1 : 0;

    cudaFuncSetAttribute(fused_kernel,
                         cudaFuncAttributeMaxDynamicSharedMemorySize, SM_TOTAL);

    zero_flags<<<1, 32>>>();
    fused_kernel<<<GRID_TOT, 256, SM_TOTAL>>>(E, W, bmu, dur, out, write_mask);
}